// round 8
// baseline (speedup 1.0000x reference)
#include <cuda_runtime.h>
#include <math.h>

// Problem constants
#define Bz    4
#define Mz    2048
#define Ez    512
#define Hz    8
#define Dz    64
#define BHz   (Bz*Hz)          // 32
#define ROWS  (Bz*Mz)          // 8192

// attention tiling
#define SSTR 2052              // S row stride (mult of 4 -> LDS.128 legal on every row)
#define JT   256               // key/value tile
#define NJT  (Mz/JT)           // 8
#define KSTR 65                // K tile row stride (odd -> conflict-free scalar LDS)
#define VSTR 68                // V tile row stride (mult of 4 -> float4 LDS/STS)
#define QTR  20                // transposed Q stride (mult of 4)

typedef unsigned long long ull;

// ---------------- packed f32x2 helpers (B300 FFMA2 path) ----------------------
__device__ __forceinline__ void ffma2(ull& acc, ull a, ull b) {
    asm("fma.rn.f32x2 %0, %1, %2, %0;" : "+l"(acc) : "l"(a), "l"(b));
}
__device__ __forceinline__ ull dup2(float v) {
    ull r;
    asm("mov.b64 %0, {%1, %1};" : "=l"(r) : "f"(v));
    return r;
}
__device__ __forceinline__ float2 unpack2(ull v) {
    float2 r;
    asm("mov.b64 {%0, %1}, %2;" : "=f"(r.x), "=f"(r.y) : "l"(v));
    return r;
}

// ---------------- scratch (device globals; no allocation allowed) ------------
__device__ float g_norm[ROWS * Ez];          // 16 MB
__device__ float g_q[BHz * Mz * Dz];         // 16 MB  [bh][m][d]
__device__ float g_k[BHz * Mz * Dz];         // 16 MB
__device__ float g_v[BHz * Mz * Dz];         // 16 MB
__device__ float g_ctx[ROWS * Ez];           // 16 MB  [b*M+m][E]

// ---------------- LayerNorm (warp-shuffle reduction) --------------------------
__global__ void ln_kernel(const float* __restrict__ x,
                          const float* __restrict__ gamma,
                          const float* __restrict__ beta) {
    int row = blockIdx.x;                 // 8192
    const float* xr = x + (size_t)row * Ez;
    int t = threadIdx.x;                  // 256
    float2 v = *(const float2*)&xr[t * 2];

    __shared__ float red[8];
    int lane = t & 31, wid = t >> 5;

    float s = v.x + v.y;
    #pragma unroll
    for (int o = 16; o > 0; o >>= 1) s += __shfl_xor_sync(0xffffffffu, s, o);
    if (lane == 0) red[wid] = s;
    __syncthreads();
    float tot = red[0];
    #pragma unroll
    for (int w = 1; w < 8; ++w) tot += red[w];
    float mean = tot * (1.0f / Ez);
    __syncthreads();

    float d0 = v.x - mean, d1 = v.y - mean;
    s = d0 * d0 + d1 * d1;
    #pragma unroll
    for (int o = 16; o > 0; o >>= 1) s += __shfl_xor_sync(0xffffffffu, s, o);
    if (lane == 0) red[wid] = s;
    __syncthreads();
    tot = red[0];
    #pragma unroll
    for (int w = 1; w < 8; ++w) tot += red[w];
    float rstd = rsqrtf(tot * (1.0f / Ez) + 1e-5f);

    float2 g = *(const float2*)&gamma[t * 2];
    float2 b = *(const float2*)&beta[t * 2];
    float2 o2 = make_float2(d0 * rstd * g.x + b.x, d1 * rstd * g.y + b.y);
    *(float2*)&g_norm[(size_t)row * Ez + t * 2] = o2;
}

// ---------------- QKV projection GEMM (NT): out = norm @ W^T + b -------------
__global__ void qkv_gemm(const float* __restrict__ wq, const float* __restrict__ bq,
                         const float* __restrict__ wk, const float* __restrict__ bk,
                         const float* __restrict__ wv, const float* __restrict__ bv) {
    const float* W;
    const float* bias;
    float* dst;
    if (blockIdx.z == 0)      { W = wq; bias = bq; dst = g_q; }
    else if (blockIdx.z == 1) { W = wk; bias = bk; dst = g_k; }
    else                      { W = wv; bias = bv; dst = g_v; }

    __shared__ float As[32][64];   // [k][m]
    __shared__ float Bs[32][64];   // [k][n]

    int bm = blockIdx.y * 64;
    int bn = blockIdx.x * 64;
    int tx = threadIdx.x;          // 16
    int ty = threadIdx.y;          // 16
    int tid = ty * 16 + tx;

    int lm  = tid >> 2;            // 0..63
    int lk0 = (tid & 3) * 8;       // 0,8,16,24

    ull acc2[4][2];                // [row i][col-pair p]
    #pragma unroll
    for (int i = 0; i < 4; ++i) { acc2[i][0] = 0ULL; acc2[i][1] = 0ULL; }

    for (int k0 = 0; k0 < Ez; k0 += 32) {
        const float* Ap = g_norm + (size_t)(bm + lm) * Ez + k0 + lk0;
        const float* Bp = W      + (size_t)(bn + lm) * Ez + k0 + lk0;
        float4 a0 = *(const float4*)(Ap);
        float4 a1 = *(const float4*)(Ap + 4);
        float4 b0 = *(const float4*)(Bp);
        float4 b1 = *(const float4*)(Bp + 4);
        As[lk0 + 0][lm] = a0.x; As[lk0 + 1][lm] = a0.y; As[lk0 + 2][lm] = a0.z; As[lk0 + 3][lm] = a0.w;
        As[lk0 + 4][lm] = a1.x; As[lk0 + 5][lm] = a1.y; As[lk0 + 6][lm] = a1.z; As[lk0 + 7][lm] = a1.w;
        Bs[lk0 + 0][lm] = b0.x; Bs[lk0 + 1][lm] = b0.y; Bs[lk0 + 2][lm] = b0.z; Bs[lk0 + 3][lm] = b0.w;
        Bs[lk0 + 4][lm] = b1.x; Bs[lk0 + 5][lm] = b1.y; Bs[lk0 + 6][lm] = b1.z; Bs[lk0 + 7][lm] = b1.w;
        __syncthreads();

        #pragma unroll
        for (int k = 0; k < 32; ++k) {
            float4 a = *(const float4*)&As[k][ty * 4];
            ulonglong2 bp = *(const ulonglong2*)&Bs[k][tx * 4];  // (b0,b1),(b2,b3)
            ull ad0 = dup2(a.x), ad1 = dup2(a.y), ad2 = dup2(a.z), ad3 = dup2(a.w);
            ffma2(acc2[0][0], ad0, bp.x); ffma2(acc2[0][1], ad0, bp.y);
            ffma2(acc2[1][0], ad1, bp.x); ffma2(acc2[1][1], ad1, bp.y);
            ffma2(acc2[2][0], ad2, bp.x); ffma2(acc2[2][1], ad2, bp.y);
            ffma2(acc2[3][0], ad3, bp.x); ffma2(acc2[3][1], ad3, bp.y);
        }
        __syncthreads();
    }

    // epilogue: 4 consecutive n share one head -> float4 store
    int n0 = bn + tx * 4;
    int h  = n0 >> 6, dd = n0 & 63;
    float4 bia = *(const float4*)&bias[n0];
    #pragma unroll
    for (int i = 0; i < 4; ++i) {
        int m  = bm + ty * 4 + i;
        int b_ = m >> 11, mm = m & 2047;
        float2 lo = unpack2(acc2[i][0]);
        float2 hi = unpack2(acc2[i][1]);
        float4 v = make_float4(lo.x + bia.x, lo.y + bia.y, hi.x + bia.z, hi.y + bia.w);
        *(float4*)&dst[(size_t)(((b_ << 3) + h) * Mz + mm) * Dz + dd] = v;
    }
}

// ---------------- fused attention: scores + mask + softmax + attn write + P@V
// One CTA per (bh, 16 q-rows). Full 16x2048 score rows live in SMEM.
__global__ void __launch_bounds__(256, 1) attn_kernel(float* __restrict__ attn_out,
                                                      int write_attn) {
    extern __shared__ float sm[];
    float* S    = sm;                       // 16 * SSTR
    float* KV   = S + 16 * SSTR;            // JT * VSTR (K uses KSTR; also PV partials)
    float* Qs   = KV + JT * VSTR;           // 64 * QTR  transposed [d][i]
    float* rmax = Qs + 64 * QTR;            // 16
    float* rsum = rmax + 16;                // 16

    int bh = blockIdx.y;                    // 32
    int q0 = blockIdx.x * 16;               // 128 tiles
    const float* Qg = g_q + (size_t)bh * Mz * Dz;
    const float* Kg = g_k + (size_t)bh * Mz * Dz;
    const float* Vg = g_v + (size_t)bh * Mz * Dz;
    int tid = threadIdx.x;                  // 256

    int cj = tid >> 4;                      // copy: j row 0..15 (stride 16)
    int cd = (tid & 15) * 4;                // copy: d quad

    // load Q tile transposed: Qs[d][i]  (vector LDG, scalar STS)
    {
        int i = tid >> 4, d0 = (tid & 15) * 4;
        float4 q = *(const float4*)&Qg[(size_t)(q0 + i) * Dz + d0];
        Qs[(d0    ) * QTR + i] = q.x;
        Qs[(d0 + 1) * QTR + i] = q.y;
        Qs[(d0 + 2) * QTR + i] = q.z;
        Qs[(d0 + 3) * QTR + i] = q.w;
    }

    const float scale = 0.125f;             // 1/sqrt(64)

    // prologue prefetch: K tile 0
    float4 pre[16];
    #pragma unroll
    for (int u = 0; u < 16; ++u)
        pre[u] = *(const float4*)&Kg[(size_t)(cj + 16 * u) * Dz + cd];
    __syncthreads();

    {
        int iy = tid >> 6;                  // 0..3  (i group of 4)
        int jx = tid & 63;                  // 0..63 (j base; columns jx+64c)

        // ---- S = Q K^T * scale ----
        for (int jt = 0; jt < NJT; ++jt) {
            int j0 = jt * JT;
            // commit prefetched K tile to smem (scalar STS, KSTR odd)
            #pragma unroll
            for (int u = 0; u < 16; ++u) {
                float* dst = &KV[(cj + 16 * u) * KSTR + cd];
                dst[0] = pre[u].x; dst[1] = pre[u].y; dst[2] = pre[u].z; dst[3] = pre[u].w;
            }
            __syncthreads();
            // prefetch next tile (K tiles 1..7, then V tile 0)
            if (jt < NJT - 1) {
                const float* src = &Kg[(size_t)(j0 + JT + cj) * Dz + cd];
                #pragma unroll
                for (int u = 0; u < 16; ++u)
                    pre[u] = *(const float4*)(src + (size_t)(16 * u) * Dz);
            } else {
                const float* src = &Vg[(size_t)cj * Dz + cd];
                #pragma unroll
                for (int u = 0; u < 16; ++u)
                    pre[u] = *(const float4*)(src + (size_t)(16 * u) * Dz);
            }

            ull acc2[2][4];                 // [row-pair][col]
            #pragma unroll
            for (int p = 0; p < 2; ++p)
                #pragma unroll
                for (int c = 0; c < 4; ++c) acc2[p][c] = 0ULL;

            #pragma unroll 4
            for (int d = 0; d < 64; ++d) {
                ulonglong2 qp = *(const ulonglong2*)&Qs[d * QTR + 4 * iy]; // (q0,q1),(q2,q3)
                ull k0 = dup2(KV[(jx      ) * KSTR + d]);
                ull k1 = dup2(KV[(jx +  64) * KSTR + d]);
                ull k2 = dup2(KV[(jx + 128) * KSTR + d]);
                ull k3 = dup2(KV[(jx + 192) * KSTR + d]);
                ffma2(acc2[0][0], qp.x, k0); ffma2(acc2[1][0], qp.y, k0);
                ffma2(acc2[0][1], qp.x, k1); ffma2(acc2[1][1], qp.y, k1);
                ffma2(acc2[0][2], qp.x, k2); ffma2(acc2[1][2], qp.y, k2);
                ffma2(acc2[0][3], qp.x, k3); ffma2(acc2[1][3], qp.y, k3);
            }

            #pragma unroll
            for (int p = 0; p < 2; ++p)
                #pragma unroll
                for (int c = 0; c < 4; ++c) {
                    float2 v = unpack2(acc2[p][c]);
                    S[(4 * iy + 2 * p    ) * SSTR + j0 + jx + 64 * c] = v.x * scale;
                    S[(4 * iy + 2 * p + 1) * SSTR + j0 + jx + 64 * c] = v.y * scale;
                }
            __syncthreads();
        }
    }

    // mask diagonal (j == global query index q0+i)
    if (tid < 16) S[tid * SSTR + q0 + tid] = -1e30f;
    __syncthreads();

    // ---- row max (vectorized LDS.128) ----
    {
        int row = tid >> 4, lane = tid & 15;
        float m = -1e30f;
        for (int j4 = lane * 4; j4 < Mz; j4 += 64) {
            float4 p = *(const float4*)&S[row * SSTR + j4];
            m = fmaxf(m, fmaxf(fmaxf(p.x, p.y), fmaxf(p.z, p.w)));
        }
        #pragma unroll
        for (int o = 8; o > 0; o >>= 1) m = fmaxf(m, __shfl_xor_sync(0xffffffffu, m, o, 16));
        if (lane == 0) rmax[row] = m;
    }
    __syncthreads();

    // ---- exp + row sum (vectorized) ----
    {
        int row = tid >> 4, lane = tid & 15;
        float mx = rmax[row];
        float s = 0.f;
        for (int j4 = lane * 4; j4 < Mz; j4 += 64) {
            float4 p = *(const float4*)&S[row * SSTR + j4];
            p.x = __expf(p.x - mx);
            p.y = __expf(p.y - mx);
            p.z = __expf(p.z - mx);
            p.w = __expf(p.w - mx);
            *(float4*)&S[row * SSTR + j4] = p;
            s += (p.x + p.y) + (p.z + p.w);
        }
        #pragma unroll
        for (int o = 8; o > 0; o >>= 1) s += __shfl_xor_sync(0xffffffffu, s, o, 16);
        if (lane == 0) rsum[row] = s;
    }
    __syncthreads();

    // ---- write normalized attn: streaming stores (evict-first, keep K/V in L2)
    if (write_attn) {
        long long base = (long long)bh * Mz * Mz + (long long)q0 * Mz;
        for (int i = 0; i < 16; ++i) {
            float inv = 1.0f / rsum[i];
            for (int j4 = tid * 4; j4 < Mz; j4 += 1024) {
                float4 p = *(const float4*)&S[i * SSTR + j4];
                float4 w = make_float4(p.x * inv, p.y * inv, p.z * inv, p.w * inv);
                __stcs((float4*)&attn_out[base + (long long)i * Mz + j4], w);
            }
        }
    }

    // ---- ctx = P @ V ----
    // Each thread: ALL 16 q-rows x 4 contiguous d, for j slice (j % 16 == jo).
    // V float4 read exactly once; partials reduced through smem afterwards.
    {
        int jo  = tid >> 4;                 // 0..15  j offset
        int dq4 = (tid & 15) * 4;           // d quad

        ull accv[16][2];
        #pragma unroll
        for (int i = 0; i < 16; ++i) { accv[i][0] = 0ULL; accv[i][1] = 0ULL; }

        for (int jt = 0; jt < NJT; ++jt) {
            int j0 = jt * JT;
            __syncthreads();                // previous KV consumers done
            // commit prefetched V tile (vector STS, VSTR mult of 4)
            #pragma unroll
            for (int u = 0; u < 16; ++u)
                *(float4*)&KV[(cj + 16 * u) * VSTR + cd] = pre[u];
            __syncthreads();
            if (jt < NJT - 1) {
                const float* src = &Vg[(size_t)(j0 + JT + cj) * Dz + cd];
                #pragma unroll
                for (int u = 0; u < 16; ++u)
                    pre[u] = *(const float4*)(src + (size_t)(16 * u) * Dz);
            }

            for (int j = jo; j < JT; j += 16) {
                ulonglong2 vp = *(const ulonglong2*)&KV[j * VSTR + dq4];
                const float* Sp = &S[j0 + j];
                #pragma unroll
                for (int i = 0; i < 16; ++i) {
                    ull pd = dup2(Sp[i * SSTR]);
                    ffma2(accv[i][0], pd, vp.x);
                    ffma2(accv[i][1], pd, vp.y);
                }
            }
        }
        __syncthreads();                    // all V reads done; reuse KV for partials

        // store partials: KV[jo*1024 + i*64 + dq4 .. +3]
        #pragma unroll
        for (int i = 0; i < 16; ++i) {
            float2 lo = unpack2(accv[i][0]);
            float2 hi = unpack2(accv[i][1]);
            *(float4*)&KV[jo * 1024 + i * 64 + dq4] = make_float4(lo.x, lo.y, hi.x, hi.y);
        }
        __syncthreads();

        // reduce 16 partials per output float4 (vectorized LDS.128), write ctx
        int b_ = bh >> 3, h = bh & 7;
        {
            int o4 = tid * 4;               // 0..1020, one float4 per thread
            int i  = o4 >> 6, d = o4 & 63;
            float4 s = *(const float4*)&KV[o4];
            #pragma unroll
            for (int p = 1; p < 16; ++p) {
                float4 q = *(const float4*)&KV[p * 1024 + o4];
                s.x += q.x; s.y += q.y; s.z += q.z; s.w += q.w;
            }
            float inv = 1.0f / rsum[i];
            float4 w = make_float4(s.x * inv, s.y * inv, s.z * inv, s.w * inv);
            *(float4*)&g_ctx[((size_t)(b_ * Mz + q0 + i)) * Ez + h * Dz + d] = w;
        }
    }
}

// ---------------- output projection + residual -------------------------------
__global__ void out_gemm(const float* __restrict__ wo, const float* __restrict__ bo,
                         const float* __restrict__ x, float* __restrict__ out) {
    __shared__ float As[32][64];
    __shared__ float Bs[32][64];

    int bm = blockIdx.y * 64;
    int bn = blockIdx.x * 64;
    int tx = threadIdx.x, ty = threadIdx.y;
    int tid = ty * 16 + tx;
    int lm = tid >> 2;
    int lk0 = (tid & 3) * 8;

    ull acc2[4][2];
    #pragma unroll
    for (int i = 0; i < 4; ++i) { acc2[i][0] = 0ULL; acc2[i][1] = 0ULL; }

    for (int k0 = 0; k0 < Ez; k0 += 32) {
        const float* Ap = g_ctx + (size_t)(bm + lm) * Ez + k0 + lk0;
        const float* Bp = wo    + (size_t)(bn + lm) * Ez + k0 + lk0;
        float4 a0 = *(const float4*)(Ap);
        float4 a1 = *(const float4*)(Ap + 4);
        float4 b0 = *(const float4*)(Bp);
        float4 b1 = *(const float4*)(Bp + 4);
        As[lk0 + 0][lm] = a0.x; As[lk0 + 1][lm] = a0.y; As[lk0 + 2][lm] = a0.z; As[lk0 + 3][lm] = a0.w;
        As[lk0 + 4][lm] = a1.x; As[lk0 + 5][lm] = a1.y; As[lk0 + 6][lm] = a1.z; As[lk0 + 7][lm] = a1.w;
        Bs[lk0 + 0][lm] = b0.x; Bs[lk0 + 1][lm] = b0.y; Bs[lk0 + 2][lm] = b0.z; Bs[lk0 + 3][lm] = b0.w;
        Bs[lk0 + 4][lm] = b1.x; Bs[lk0 + 5][lm] = b1.y; Bs[lk0 + 6][lm] = b1.z; Bs[lk0 + 7][lm] = b1.w;
        __syncthreads();
        #pragma unroll
        for (int k = 0; k < 32; ++k) {
            float4 a = *(const float4*)&As[k][ty * 4];
            ulonglong2 bp = *(const ulonglong2*)&Bs[k][tx * 4];
            ull ad0 = dup2(a.x), ad1 = dup2(a.y), ad2 = dup2(a.z), ad3 = dup2(a.w);
            ffma2(acc2[0][0], ad0, bp.x); ffma2(acc2[0][1], ad0, bp.y);
            ffma2(acc2[1][0], ad1, bp.x); ffma2(acc2[1][1], ad1, bp.y);
            ffma2(acc2[2][0], ad2, bp.x); ffma2(acc2[2][1], ad2, bp.y);
            ffma2(acc2[3][0], ad3, bp.x); ffma2(acc2[3][1], ad3, bp.y);
        }
        __syncthreads();
    }

    int n0 = bn + tx * 4;
    float4 bia = *(const float4*)&bo[n0];
    #pragma unroll
    for (int i = 0; i < 4; ++i) {
        int m = bm + ty * 4 + i;
        float2 lo = unpack2(acc2[i][0]);
        float2 hi = unpack2(acc2[i][1]);
        float4 xr = *(const float4*)&x[(size_t)m * Ez + n0];
        float4 v = make_float4(lo.x + bia.x + xr.x, lo.y + bia.y + xr.y,
                               hi.x + bia.z + xr.z, hi.y + bia.w + xr.w);
        *(float4*)&out[(size_t)m * Ez + n0] = v;
    }
}

// ---------------- launch ------------------------------------------------------
extern "C" void kernel_launch(void* const* d_in, const int* in_sizes, int n_in,
                              void* d_out, int out_size) {
    const float* x     = (const float*)d_in[0];
    const float* wq    = (const float*)d_in[1];
    const float* bq    = (const float*)d_in[2];
    const float* wk    = (const float*)d_in[3];
    const float* bk    = (const float*)d_in[4];
    const float* wv    = (const float*)d_in[5];
    const float* bv    = (const float*)d_in[6];
    const float* wo    = (const float*)d_in[7];
    const float* bo    = (const float*)d_in[8];
    const float* gamma = (const float*)d_in[9];
    const float* beta  = (const float*)d_in[10];
    float* out = (float*)d_out;

    const long long OUT0 = (long long)Bz * Mz * Ez;   // 4,194,304
    int write_attn = ((long long)out_size > OUT0) ? 1 : 0;
    float* attn_ptr = out + OUT0;

    // 1. LayerNorm
    ln_kernel<<<ROWS, 256>>>(x, gamma, beta);

    // 2. Q,K,V projections
    qkv_gemm<<<dim3(Ez / 64, ROWS / 64, 3), dim3(16, 16)>>>(wq, bq, wk, bk, wv, bv);

    // 3. fused attention (scores + softmax + attn write + P@V)
    const int SMEM_BYTES = (16 * SSTR + JT * VSTR + 64 * QTR + 32) * (int)sizeof(float);
    cudaFuncSetAttribute(attn_kernel, cudaFuncAttributeMaxDynamicSharedMemorySize, SMEM_BYTES);
    attn_kernel<<<dim3(Mz / 16, BHz), 256, SMEM_BYTES>>>(attn_ptr, write_attn);

    // 4. output projection + residual
    out_gemm<<<dim3(Ez / 64, ROWS / 64), dim3(16, 16)>>>(wo, bo, x, out);
}

// round 9
// speedup vs baseline: 1.0593x; 1.0593x over previous
#include <cuda_runtime.h>
#include <math.h>

// Problem constants
#define Bz    4
#define Mz    2048
#define Ez    512
#define Hz    8
#define Dz    64
#define BHz   (Bz*Hz)          // 32
#define ROWS  (Bz*Mz)          // 8192

// attention tiling
#define SSTR 2052              // S row stride (mult of 4 -> LDS.128 legal on every row)
#define JT   256               // key/value tile
#define NJT  (Mz/JT)           // 8
#define KSTR 65                // K tile row stride (odd -> conflict-free scalar LDS)
#define VSTR 68                // V tile row stride (mult of 4 -> float4 LDS/STS)
#define QTR  20                // transposed Q stride (mult of 4)

// GEMM tiling (128x128 tile, 8x8 microtile, k-tile 16)
#define TK   16
#define AST  132               // smem row stride: mult of 4 (LDS.128) + tolerable STS conflicts

typedef unsigned long long ull;

// ---------------- packed f32x2 helpers (B300 FFMA2 path) ----------------------
__device__ __forceinline__ void ffma2(ull& acc, ull a, ull b) {
    asm("fma.rn.f32x2 %0, %1, %2, %0;" : "+l"(acc) : "l"(a), "l"(b));
}
__device__ __forceinline__ ull dup2(float v) {
    ull r;
    asm("mov.b64 %0, {%1, %1};" : "=l"(r) : "f"(v));
    return r;
}
__device__ __forceinline__ float2 unpack2(ull v) {
    float2 r;
    asm("mov.b64 {%0, %1}, %2;" : "=f"(r.x), "=f"(r.y) : "l"(v));
    return r;
}

// ---------------- scratch (device globals; no allocation allowed) ------------
__device__ float g_norm[ROWS * Ez];          // 16 MB
__device__ float g_q[BHz * Mz * Dz];         // 16 MB  [bh][m][d]
__device__ float g_k[BHz * Mz * Dz];         // 16 MB
__device__ float g_v[BHz * Mz * Dz];         // 16 MB
__device__ float g_ctx[ROWS * Ez];           // 16 MB  [b*M+m][E]

// ---------------- LayerNorm (warp-shuffle reduction) --------------------------
__global__ void ln_kernel(const float* __restrict__ x,
                          const float* __restrict__ gamma,
                          const float* __restrict__ beta) {
    int row = blockIdx.x;                 // 8192
    const float* xr = x + (size_t)row * Ez;
    int t = threadIdx.x;                  // 256
    float2 v = *(const float2*)&xr[t * 2];

    __shared__ float red[8];
    int lane = t & 31, wid = t >> 5;

    float s = v.x + v.y;
    #pragma unroll
    for (int o = 16; o > 0; o >>= 1) s += __shfl_xor_sync(0xffffffffu, s, o);
    if (lane == 0) red[wid] = s;
    __syncthreads();
    float tot = red[0];
    #pragma unroll
    for (int w = 1; w < 8; ++w) tot += red[w];
    float mean = tot * (1.0f / Ez);
    __syncthreads();

    float d0 = v.x - mean, d1 = v.y - mean;
    s = d0 * d0 + d1 * d1;
    #pragma unroll
    for (int o = 16; o > 0; o >>= 1) s += __shfl_xor_sync(0xffffffffu, s, o);
    if (lane == 0) red[wid] = s;
    __syncthreads();
    tot = red[0];
    #pragma unroll
    for (int w = 1; w < 8; ++w) tot += red[w];
    float rstd = rsqrtf(tot * (1.0f / Ez) + 1e-5f);

    float2 g = *(const float2*)&gamma[t * 2];
    float2 b = *(const float2*)&beta[t * 2];
    float2 o2 = make_float2(d0 * rstd * g.x + b.x, d1 * rstd * g.y + b.y);
    *(float2*)&g_norm[(size_t)row * Ez + t * 2] = o2;
}

// ---------------- 128x128 GEMM core (NT): C = A @ W^T -------------------------
// 256 threads, 8x8 microtile, 1 B/FMA smem traffic -> FFMA2-rate bound.
// Copy: thread (cr=tid>>2, cq=(tid&3)*4) loads rows cr, cr+64, k-quad cq.
struct GemmAcc { ull a[8][4]; };

__device__ __forceinline__ void gemm_mainloop(
    GemmAcc& G, const float* __restrict__ A, const float* __restrict__ W,
    int bm, int bn, float (*As)[AST], float (*Bs)[AST],
    int tid, int ty, int tx)
{
    int cr = tid >> 2;             // 0..63
    int cq = (tid & 3) * 4;        // 0,4,8,12 (k offset)

    const float* Ap = A + (size_t)(bm + cr) * Ez + cq;
    const float* Bp = W + (size_t)(bn + cr) * Ez + cq;

    float4 pa0 = *(const float4*)(Ap);
    float4 pa1 = *(const float4*)(Ap + (size_t)64 * Ez);
    float4 pb0 = *(const float4*)(Bp);
    float4 pb1 = *(const float4*)(Bp + (size_t)64 * Ez);

    for (int k0 = 0; k0 < Ez; k0 += TK) {
        __syncthreads();           // previous compute done
        As[cq + 0][cr] = pa0.x; As[cq + 1][cr] = pa0.y;
        As[cq + 2][cr] = pa0.z; As[cq + 3][cr] = pa0.w;
        As[cq + 0][cr + 64] = pa1.x; As[cq + 1][cr + 64] = pa1.y;
        As[cq + 2][cr + 64] = pa1.z; As[cq + 3][cr + 64] = pa1.w;
        Bs[cq + 0][cr] = pb0.x; Bs[cq + 1][cr] = pb0.y;
        Bs[cq + 2][cr] = pb0.z; Bs[cq + 3][cr] = pb0.w;
        Bs[cq + 0][cr + 64] = pb1.x; Bs[cq + 1][cr + 64] = pb1.y;
        Bs[cq + 2][cr + 64] = pb1.z; Bs[cq + 3][cr + 64] = pb1.w;
        __syncthreads();

        if (k0 + TK < Ez) {        // prefetch next k-tile
            Ap += TK; Bp += TK;
            pa0 = *(const float4*)(Ap);
            pa1 = *(const float4*)(Ap + (size_t)64 * Ez);
            pb0 = *(const float4*)(Bp);
            pb1 = *(const float4*)(Bp + (size_t)64 * Ez);
        }

        #pragma unroll
        for (int k = 0; k < TK; ++k) {
            float4 a0 = *(const float4*)&As[k][ty * 8];
            float4 a1 = *(const float4*)&As[k][ty * 8 + 4];
            ulonglong2 b0 = *(const ulonglong2*)&Bs[k][tx * 8];
            ulonglong2 b1 = *(const ulonglong2*)&Bs[k][tx * 8 + 4];
            ull d0 = dup2(a0.x), d1 = dup2(a0.y), d2 = dup2(a0.z), d3 = dup2(a0.w);
            ull d4 = dup2(a1.x), d5 = dup2(a1.y), d6 = dup2(a1.z), d7 = dup2(a1.w);
            ffma2(G.a[0][0], d0, b0.x); ffma2(G.a[0][1], d0, b0.y);
            ffma2(G.a[0][2], d0, b1.x); ffma2(G.a[0][3], d0, b1.y);
            ffma2(G.a[1][0], d1, b0.x); ffma2(G.a[1][1], d1, b0.y);
            ffma2(G.a[1][2], d1, b1.x); ffma2(G.a[1][3], d1, b1.y);
            ffma2(G.a[2][0], d2, b0.x); ffma2(G.a[2][1], d2, b0.y);
            ffma2(G.a[2][2], d2, b1.x); ffma2(G.a[2][3], d2, b1.y);
            ffma2(G.a[3][0], d3, b0.x); ffma2(G.a[3][1], d3, b0.y);
            ffma2(G.a[3][2], d3, b1.x); ffma2(G.a[3][3], d3, b1.y);
            ffma2(G.a[4][0], d4, b0.x); ffma2(G.a[4][1], d4, b0.y);
            ffma2(G.a[4][2], d4, b1.x); ffma2(G.a[4][3], d4, b1.y);
            ffma2(G.a[5][0], d5, b0.x); ffma2(G.a[5][1], d5, b0.y);
            ffma2(G.a[5][2], d5, b1.x); ffma2(G.a[5][3], d5, b1.y);
            ffma2(G.a[6][0], d6, b0.x); ffma2(G.a[6][1], d6, b0.y);
            ffma2(G.a[6][2], d6, b1.x); ffma2(G.a[6][3], d6, b1.y);
            ffma2(G.a[7][0], d7, b0.x); ffma2(G.a[7][1], d7, b0.y);
            ffma2(G.a[7][2], d7, b1.x); ffma2(G.a[7][3], d7, b1.y);
        }
    }
}

// ---------------- QKV projection GEMM: out = norm @ W^T + b, head scatter ----
__global__ void __launch_bounds__(256, 2) qkv_gemm(
        const float* __restrict__ wq, const float* __restrict__ bq,
        const float* __restrict__ wk, const float* __restrict__ bk,
        const float* __restrict__ wv, const float* __restrict__ bv) {
    const float* W;
    const float* bias;
    float* dst;
    if (blockIdx.z == 0)      { W = wq; bias = bq; dst = g_q; }
    else if (blockIdx.z == 1) { W = wk; bias = bk; dst = g_k; }
    else                      { W = wv; bias = bv; dst = g_v; }

    __shared__ float As[TK][AST];
    __shared__ float Bs[TK][AST];

    int bm = blockIdx.y * 128;
    int bn = blockIdx.x * 128;
    int tid = threadIdx.x;
    int ty = tid >> 4, tx = tid & 15;

    GemmAcc G;
    #pragma unroll
    for (int i = 0; i < 8; ++i)
        #pragma unroll
        for (int p = 0; p < 4; ++p) G.a[i][p] = 0ULL;

    gemm_mainloop(G, g_norm, W, bm, bn, As, Bs, tid, ty, tx);

    // epilogue: 8 consecutive n stay within one head (n0 mult of 8 < 64-bound)
    int n0 = bn + tx * 8;
    int h  = n0 >> 6, d0 = n0 & 63;
    float4 bia0 = *(const float4*)&bias[n0];
    float4 bia1 = *(const float4*)&bias[n0 + 4];
    #pragma unroll
    for (int i = 0; i < 8; ++i) {
        int m  = bm + ty * 8 + i;
        int b_ = m >> 11, mm = m & 2047;
        float2 c0 = unpack2(G.a[i][0]);
        float2 c1 = unpack2(G.a[i][1]);
        float2 c2 = unpack2(G.a[i][2]);
        float2 c3 = unpack2(G.a[i][3]);
        float4 v0 = make_float4(c0.x + bia0.x, c0.y + bia0.y, c1.x + bia0.z, c1.y + bia0.w);
        float4 v1 = make_float4(c2.x + bia1.x, c2.y + bia1.y, c3.x + bia1.z, c3.y + bia1.w);
        float* o = &dst[(size_t)(((b_ << 3) + h) * Mz + mm) * Dz + d0];
        *(float4*)(o)     = v0;
        *(float4*)(o + 4) = v1;
    }
}

// ---------------- output projection + residual -------------------------------
__global__ void __launch_bounds__(256, 2) out_gemm(
        const float* __restrict__ wo, const float* __restrict__ bo,
        const float* __restrict__ x, float* __restrict__ out) {
    __shared__ float As[TK][AST];
    __shared__ float Bs[TK][AST];

    int bm = blockIdx.y * 128;
    int bn = blockIdx.x * 128;
    int tid = threadIdx.x;
    int ty = tid >> 4, tx = tid & 15;

    GemmAcc G;
    #pragma unroll
    for (int i = 0; i < 8; ++i)
        #pragma unroll
        for (int p = 0; p < 4; ++p) G.a[i][p] = 0ULL;

    gemm_mainloop(G, g_ctx, wo, bm, bn, As, Bs, tid, ty, tx);

    int n0 = bn + tx * 8;
    float4 bia0 = *(const float4*)&bo[n0];
    float4 bia1 = *(const float4*)&bo[n0 + 4];
    #pragma unroll
    for (int i = 0; i < 8; ++i) {
        int m = bm + ty * 8 + i;
        float2 c0 = unpack2(G.a[i][0]);
        float2 c1 = unpack2(G.a[i][1]);
        float2 c2 = unpack2(G.a[i][2]);
        float2 c3 = unpack2(G.a[i][3]);
        float4 x0 = *(const float4*)&x[(size_t)m * Ez + n0];
        float4 x1 = *(const float4*)&x[(size_t)m * Ez + n0 + 4];
        float4 v0 = make_float4(c0.x + bia0.x + x0.x, c0.y + bia0.y + x0.y,
                                c1.x + bia0.z + x0.z, c1.y + bia0.w + x0.w);
        float4 v1 = make_float4(c2.x + bia1.x + x1.x, c2.y + bia1.y + x1.y,
                                c3.x + bia1.z + x1.z, c3.y + bia1.w + x1.w);
        *(float4*)&out[(size_t)m * Ez + n0]     = v0;
        *(float4*)&out[(size_t)m * Ez + n0 + 4] = v1;
    }
}

// ---------------- fused attention: scores + mask + softmax + attn write + P@V
// One CTA per (bh, 16 q-rows). Full 16x2048 score rows live in SMEM.
// (unchanged from the passing R7 kernel)
__global__ void __launch_bounds__(256, 1) attn_kernel(float* __restrict__ attn_out,
                                                      int write_attn) {
    extern __shared__ float sm[];
    float* S    = sm;                       // 16 * SSTR
    float* KV   = S + 16 * SSTR;            // JT * VSTR (K uses KSTR; also PV partials)
    float* Qs   = KV + JT * VSTR;           // 64 * QTR  transposed [d][i]
    float* rmax = Qs + 64 * QTR;            // 16
    float* rsum = rmax + 16;                // 16

    int bh = blockIdx.y;                    // 32
    int q0 = blockIdx.x * 16;               // 128 tiles
    const float* Qg = g_q + (size_t)bh * Mz * Dz;
    const float* Kg = g_k + (size_t)bh * Mz * Dz;
    const float* Vg = g_v + (size_t)bh * Mz * Dz;
    int tid = threadIdx.x;                  // 256

    int cj = tid >> 4;                      // copy: j row 0..15 (stride 16)
    int cd = (tid & 15) * 4;                // copy: d quad

    // load Q tile transposed: Qs[d][i]  (vector LDG, scalar STS)
    {
        int i = tid >> 4, d0 = (tid & 15) * 4;
        float4 q = *(const float4*)&Qg[(size_t)(q0 + i) * Dz + d0];
        Qs[(d0    ) * QTR + i] = q.x;
        Qs[(d0 + 1) * QTR + i] = q.y;
        Qs[(d0 + 2) * QTR + i] = q.z;
        Qs[(d0 + 3) * QTR + i] = q.w;
    }

    const float scale = 0.125f;             // 1/sqrt(64)

    // prologue prefetch: K tile 0
    float4 pre[16];
    #pragma unroll
    for (int u = 0; u < 16; ++u)
        pre[u] = *(const float4*)&Kg[(size_t)(cj + 16 * u) * Dz + cd];
    __syncthreads();

    {
        int iy = tid >> 6;                  // 0..3  (i group of 4)
        int jx = tid & 63;                  // 0..63 (j base; columns jx+64c)

        // ---- S = Q K^T * scale ----
        for (int jt = 0; jt < NJT; ++jt) {
            int j0 = jt * JT;
            // commit prefetched K tile to smem (scalar STS, KSTR odd)
            #pragma unroll
            for (int u = 0; u < 16; ++u) {
                float* dst = &KV[(cj + 16 * u) * KSTR + cd];
                dst[0] = pre[u].x; dst[1] = pre[u].y; dst[2] = pre[u].z; dst[3] = pre[u].w;
            }
            __syncthreads();
            // prefetch next tile (K tiles 1..7, then V tile 0)
            if (jt < NJT - 1) {
                const float* src = &Kg[(size_t)(j0 + JT + cj) * Dz + cd];
                #pragma unroll
                for (int u = 0; u < 16; ++u)
                    pre[u] = *(const float4*)(src + (size_t)(16 * u) * Dz);
            } else {
                const float* src = &Vg[(size_t)cj * Dz + cd];
                #pragma unroll
                for (int u = 0; u < 16; ++u)
                    pre[u] = *(const float4*)(src + (size_t)(16 * u) * Dz);
            }

            ull acc2[2][4];                 // [row-pair][col]
            #pragma unroll
            for (int p = 0; p < 2; ++p)
                #pragma unroll
                for (int c = 0; c < 4; ++c) acc2[p][c] = 0ULL;

            #pragma unroll 4
            for (int d = 0; d < 64; ++d) {
                ulonglong2 qp = *(const ulonglong2*)&Qs[d * QTR + 4 * iy]; // (q0,q1),(q2,q3)
                ull k0 = dup2(KV[(jx      ) * KSTR + d]);
                ull k1 = dup2(KV[(jx +  64) * KSTR + d]);
                ull k2 = dup2(KV[(jx + 128) * KSTR + d]);
                ull k3 = dup2(KV[(jx + 192) * KSTR + d]);
                ffma2(acc2[0][0], qp.x, k0); ffma2(acc2[1][0], qp.y, k0);
                ffma2(acc2[0][1], qp.x, k1); ffma2(acc2[1][1], qp.y, k1);
                ffma2(acc2[0][2], qp.x, k2); ffma2(acc2[1][2], qp.y, k2);
                ffma2(acc2[0][3], qp.x, k3); ffma2(acc2[1][3], qp.y, k3);
            }

            #pragma unroll
            for (int p = 0; p < 2; ++p)
                #pragma unroll
                for (int c = 0; c < 4; ++c) {
                    float2 v = unpack2(acc2[p][c]);
                    S[(4 * iy + 2 * p    ) * SSTR + j0 + jx + 64 * c] = v.x * scale;
                    S[(4 * iy + 2 * p + 1) * SSTR + j0 + jx + 64 * c] = v.y * scale;
                }
            __syncthreads();
        }
    }

    // mask diagonal (j == global query index q0+i)
    if (tid < 16) S[tid * SSTR + q0 + tid] = -1e30f;
    __syncthreads();

    // ---- row max (vectorized LDS.128) ----
    {
        int row = tid >> 4, lane = tid & 15;
        float m = -1e30f;
        for (int j4 = lane * 4; j4 < Mz; j4 += 64) {
            float4 p = *(const float4*)&S[row * SSTR + j4];
            m = fmaxf(m, fmaxf(fmaxf(p.x, p.y), fmaxf(p.z, p.w)));
        }
        #pragma unroll
        for (int o = 8; o > 0; o >>= 1) m = fmaxf(m, __shfl_xor_sync(0xffffffffu, m, o, 16));
        if (lane == 0) rmax[row] = m;
    }
    __syncthreads();

    // ---- exp + row sum (vectorized) ----
    {
        int row = tid >> 4, lane = tid & 15;
        float mx = rmax[row];
        float s = 0.f;
        for (int j4 = lane * 4; j4 < Mz; j4 += 64) {
            float4 p = *(const float4*)&S[row * SSTR + j4];
            p.x = __expf(p.x - mx);
            p.y = __expf(p.y - mx);
            p.z = __expf(p.z - mx);
            p.w = __expf(p.w - mx);
            *(float4*)&S[row * SSTR + j4] = p;
            s += (p.x + p.y) + (p.z + p.w);
        }
        #pragma unroll
        for (int o = 8; o > 0; o >>= 1) s += __shfl_xor_sync(0xffffffffu, s, o, 16);
        if (lane == 0) rsum[row] = s;
    }
    __syncthreads();

    // ---- write normalized attn: streaming stores (evict-first, keep K/V in L2)
    if (write_attn) {
        long long base = (long long)bh * Mz * Mz + (long long)q0 * Mz;
        for (int i = 0; i < 16; ++i) {
            float inv = 1.0f / rsum[i];
            for (int j4 = tid * 4; j4 < Mz; j4 += 1024) {
                float4 p = *(const float4*)&S[i * SSTR + j4];
                float4 w = make_float4(p.x * inv, p.y * inv, p.z * inv, p.w * inv);
                __stcs((float4*)&attn_out[base + (long long)i * Mz + j4], w);
            }
        }
    }

    // ---- ctx = P @ V ----
    {
        int jo  = tid >> 4;                 // 0..15  j offset
        int dq4 = (tid & 15) * 4;           // d quad

        ull accv[16][2];
        #pragma unroll
        for (int i = 0; i < 16; ++i) { accv[i][0] = 0ULL; accv[i][1] = 0ULL; }

        for (int jt = 0; jt < NJT; ++jt) {
            int j0 = jt * JT;
            __syncthreads();                // previous KV consumers done
            #pragma unroll
            for (int u = 0; u < 16; ++u)
                *(float4*)&KV[(cj + 16 * u) * VSTR + cd] = pre[u];
            __syncthreads();
            if (jt < NJT - 1) {
                const float* src = &Vg[(size_t)(j0 + JT + cj) * Dz + cd];
                #pragma unroll
                for (int u = 0; u < 16; ++u)
                    pre[u] = *(const float4*)(src + (size_t)(16 * u) * Dz);
            }

            for (int j = jo; j < JT; j += 16) {
                ulonglong2 vp = *(const ulonglong2*)&KV[j * VSTR + dq4];
                const float* Sp = &S[j0 + j];
                #pragma unroll
                for (int i = 0; i < 16; ++i) {
                    ull pd = dup2(Sp[i * SSTR]);
                    ffma2(accv[i][0], pd, vp.x);
                    ffma2(accv[i][1], pd, vp.y);
                }
            }
        }
        __syncthreads();                    // all V reads done; reuse KV for partials

        #pragma unroll
        for (int i = 0; i < 16; ++i) {
            float2 lo = unpack2(accv[i][0]);
            float2 hi = unpack2(accv[i][1]);
            *(float4*)&KV[jo * 1024 + i * 64 + dq4] = make_float4(lo.x, lo.y, hi.x, hi.y);
        }
        __syncthreads();

        // reduce 16 partials per output float4 (vectorized LDS.128), write ctx
        int b_ = bh >> 3, h = bh & 7;
        {
            int o4 = tid * 4;               // 0..1020, one float4 per thread
            int i  = o4 >> 6, d = o4 & 63;
            float4 s = *(const float4*)&KV[o4];
            #pragma unroll
            for (int p = 1; p < 16; ++p) {
                float4 q = *(const float4*)&KV[p * 1024 + o4];
                s.x += q.x; s.y += q.y; s.z += q.z; s.w += q.w;
            }
            float inv = 1.0f / rsum[i];
            float4 w = make_float4(s.x * inv, s.y * inv, s.z * inv, s.w * inv);
            *(float4*)&g_ctx[((size_t)(b_ * Mz + q0 + i)) * Ez + h * Dz + d] = w;
        }
    }
}

// ---------------- launch ------------------------------------------------------
extern "C" void kernel_launch(void* const* d_in, const int* in_sizes, int n_in,
                              void* d_out, int out_size) {
    const float* x     = (const float*)d_in[0];
    const float* wq    = (const float*)d_in[1];
    const float* bq    = (const float*)d_in[2];
    const float* wk    = (const float*)d_in[3];
    const float* bk    = (const float*)d_in[4];
    const float* wv    = (const float*)d_in[5];
    const float* bv    = (const float*)d_in[6];
    const float* wo    = (const float*)d_in[7];
    const float* bo    = (const float*)d_in[8];
    const float* gamma = (const float*)d_in[9];
    const float* beta  = (const float*)d_in[10];
    float* out = (float*)d_out;

    const long long OUT0 = (long long)Bz * Mz * Ez;   // 4,194,304
    int write_attn = ((long long)out_size > OUT0) ? 1 : 0;
    float* attn_ptr = out + OUT0;

    // 1. LayerNorm
    ln_kernel<<<ROWS, 256>>>(x, gamma, beta);

    // 2. Q,K,V projections (128x128 tiles)
    qkv_gemm<<<dim3(Ez / 128, ROWS / 128, 3), 256>>>(wq, bq, wk, bk, wv, bv);

    // 3. fused attention (scores + softmax + attn write + P@V)
    const int SMEM_BYTES = (16 * SSTR + JT * VSTR + 64 * QTR + 32) * (int)sizeof(float);
    cudaFuncSetAttribute(attn_kernel, cudaFuncAttributeMaxDynamicSharedMemorySize, SMEM_BYTES);
    attn_kernel<<<dim3(Mz / 16, BHz), 256, SMEM_BYTES>>>(attn_ptr, write_attn);

    // 4. output projection + residual (128x128 tiles)
    out_gemm<<<dim3(Ez / 128, ROWS / 128), 256>>>(wo, bo, x, out);
}